// round 1
// baseline (speedup 1.0000x reference)
#include <cuda_runtime.h>
#include <math.h>

#define LSEQ 1024
#define CEMB 1024
#define BB   8
#define NH   16
#define DH   64
#define NGRP 32

// ---------------- static scratch (device globals; no allocation) -------------
__device__ float g_x  [(size_t)BB * CEMB * LSEQ];        // 32 MB
__device__ float g_h  [(size_t)BB * CEMB * LSEQ];        // 32 MB
__device__ float g_qkv[(size_t)BB * 3 * CEMB * LSEQ];    // 96 MB
__device__ float g_att[(size_t)BB * NH * LSEQ * LSEQ];   // 512 MB
__device__ float g_ao [(size_t)BB * CEMB * LSEQ];        // 32 MB

__device__ __forceinline__ void fma44(float (&acc)[4][4], float4 a, float4 b) {
    acc[0][0] += a.x * b.x; acc[0][1] += a.x * b.y; acc[0][2] += a.x * b.z; acc[0][3] += a.x * b.w;
    acc[1][0] += a.y * b.x; acc[1][1] += a.y * b.y; acc[1][2] += a.y * b.z; acc[1][3] += a.y * b.w;
    acc[2][0] += a.z * b.x; acc[2][1] += a.z * b.y; acc[2][2] += a.z * b.z; acc[2][3] += a.z * b.w;
    acc[3][0] += a.w * b.x; acc[3][1] += a.w * b.y; acc[3][2] += a.w * b.z; acc[3][3] += a.w * b.w;
}

// ---------------- init projection: x[b,o,l] = sum_c W[o,c]*speech[b,c,l]+b[o]
// grid (LSEQ/128, CEMB/16, BB), block 128
__global__ void init_gemm(const float* __restrict__ speech, const float* __restrict__ W,
                          const float* __restrict__ bias, float* __restrict__ x) {
    __shared__ float Ws[16][80];
    __shared__ float Bs[16];
    int l  = blockIdx.x * 128 + threadIdx.x;
    int o0 = blockIdx.y * 16;
    int b  = blockIdx.z;
    for (int i = threadIdx.x; i < 16 * 80; i += 128)
        Ws[i / 80][i % 80] = W[(size_t)(o0 + i / 80) * 80 + (i % 80)];
    if (threadIdx.x < 16) Bs[threadIdx.x] = bias[o0 + threadIdx.x];
    __syncthreads();

    float acc[16];
    #pragma unroll
    for (int i = 0; i < 16; i++) acc[i] = Bs[i];
    const float* sp = speech + (size_t)b * 80 * LSEQ + l;
    for (int c = 0; c < 80; c++) {
        float sv = sp[(size_t)c * LSEQ];
        #pragma unroll
        for (int i = 0; i < 16; i++) acc[i] += Ws[i][c] * sv;
    }
    float* xp = x + ((size_t)b * CEMB + o0) * LSEQ + l;
    #pragma unroll
    for (int i = 0; i < 16; i++) xp[(size_t)i * LSEQ] = acc[i];
}

// ---------------- GroupNorm: one block per (b,g); 32 channels x 1024 --------
// grid 256, block 256
__global__ void group_norm_k(const float* __restrict__ x, const float* __restrict__ w,
                             const float* __restrict__ bb, float* __restrict__ h) {
    int bg = blockIdx.x;
    int b = bg >> 5, g = bg & 31;
    const float* xp = x + ((size_t)b * CEMB + g * 32) * LSEQ;
    float s = 0.f, ss = 0.f;
    for (int i = threadIdx.x; i < 32 * LSEQ; i += 256) {
        float v = xp[i];
        s += v; ss += v * v;
    }
    #pragma unroll
    for (int o = 16; o; o >>= 1) {
        s  += __shfl_down_sync(0xffffffffu, s,  o);
        ss += __shfl_down_sync(0xffffffffu, ss, o);
    }
    __shared__ float shs[8], shss[8];
    __shared__ float smean, srstd;
    int wid = threadIdx.x >> 5, lane = threadIdx.x & 31;
    if (!lane) { shs[wid] = s; shss[wid] = ss; }
    __syncthreads();
    if (threadIdx.x == 0) {
        float S = 0.f, SS = 0.f;
        #pragma unroll
        for (int i = 0; i < 8; i++) { S += shs[i]; SS += shss[i]; }
        float mean = S / 32768.f;
        float var  = SS / 32768.f - mean * mean;
        smean = mean;
        srstd = rsqrtf(var + 1e-5f);
    }
    __syncthreads();
    float mean = smean, rstd = srstd;
    float* hp = h + ((size_t)b * CEMB + g * 32) * LSEQ;
    for (int i = threadIdx.x; i < 32 * LSEQ; i += 256) {
        int c = g * 32 + (i >> 10);
        hp[i] = (xp[i] - mean) * rstd * w[c] + bb[c];
    }
}

// ---------------- generic Y[b,o,l] = sum_k W[o,k] X[b,k,l] + bias[o] (+res) --
// block 256 (16x16), tile 64x64, BK=16; grid (LSEQ/64, O/64, BB)
template <bool RES>
__global__ void gemm_wx(const float* __restrict__ W, const float* __restrict__ bias,
                        const float* __restrict__ X, const float* __restrict__ res,
                        float* __restrict__ Y, int O, int K) {
    __shared__ float Ws[16][64];
    __shared__ float Xs[16][64];
    int tid = threadIdx.x;
    int tx = tid & 15, ty = tid >> 4;
    int l0 = blockIdx.x << 6, o0 = blockIdx.y << 6;
    int b = blockIdx.z;
    const float* Xb = X + (size_t)b * K * LSEQ;

    int wr = tid >> 2, wc = (tid & 3) << 2;          // W loader: 64 rows x 4 f4
    int xr = tid >> 4, xc = (tid & 15) << 2;         // X loader: 16 rows x 16 f4
    const float* Wp = W + (size_t)(o0 + wr) * K + wc;
    const float* Xp = Xb + (size_t)xr * LSEQ + l0 + xc;

    float acc[4][4] = {};
    for (int k0 = 0; k0 < K; k0 += 16) {
        float4 w4 = *(const float4*)(Wp + k0);
        Ws[wc + 0][wr] = w4.x; Ws[wc + 1][wr] = w4.y;
        Ws[wc + 2][wr] = w4.z; Ws[wc + 3][wr] = w4.w;
        float4 x4 = *(const float4*)(Xp + (size_t)k0 * LSEQ);
        *(float4*)&Xs[xr][xc] = x4;
        __syncthreads();
        #pragma unroll
        for (int k = 0; k < 16; k++) {
            float4 a  = *(const float4*)&Ws[k][ty << 2];
            float4 bv = *(const float4*)&Xs[k][tx << 2];
            fma44(acc, a, bv);
        }
        __syncthreads();
    }
    #pragma unroll
    for (int i = 0; i < 4; i++) {
        int o = o0 + (ty << 2) + i;
        size_t base = ((size_t)b * O + o) * LSEQ + l0 + (tx << 2);
        float bsv = bias[o];
        float4 v = make_float4(acc[i][0] + bsv, acc[i][1] + bsv,
                               acc[i][2] + bsv, acc[i][3] + bsv);
        if (RES) {
            float4 r = *(const float4*)(res + base);
            v.x += r.x; v.y += r.y; v.z += r.z; v.w += r.w;
        }
        *(float4*)(Y + base) = v;
    }
}

// ---------------- att[bh,t,s] = 0.125 * sum_c q[c,t] k[c,s] -----------------
// block 256, tile 64x64, full K=64 in smem; grid (LSEQ/64, LSEQ/64, BB*NH)
__global__ void attn_scores(const float* __restrict__ qkv, float* __restrict__ att) {
    __shared__ float Qs[64][64];
    __shared__ float Ks[64][64];
    int bh = blockIdx.z;
    int b = bh >> 4, hh = bh & 15;
    const float* Q  = qkv + ((size_t)b * 3 * CEMB + hh * 192) * LSEQ;
    const float* Kp = Q + (size_t)DH * LSEQ;
    int t0 = blockIdx.y << 6, s0 = blockIdx.x << 6;
    int tid = threadIdx.x, tx = tid & 15, ty = tid >> 4;

    int col4 = (tid & 15) << 2;
    int rbase = tid >> 4;
    #pragma unroll
    for (int rr = 0; rr < 4; rr++) {
        int row = rr * 16 + rbase;  // channel c
        *(float4*)&Qs[row][col4] = *(const float4*)&Q [(size_t)row * LSEQ + t0 + col4];
        *(float4*)&Ks[row][col4] = *(const float4*)&Kp[(size_t)row * LSEQ + s0 + col4];
    }
    __syncthreads();

    float acc[4][4] = {};
    #pragma unroll 16
    for (int c = 0; c < 64; c++) {
        float4 a  = *(const float4*)&Qs[c][ty << 2];
        float4 bv = *(const float4*)&Ks[c][tx << 2];
        fma44(acc, a, bv);
    }
    #pragma unroll
    for (int i = 0; i < 4; i++) {
        size_t base = ((size_t)bh * LSEQ + t0 + (ty << 2) + i) * LSEQ + s0 + (tx << 2);
        float4 v = make_float4(acc[i][0] * 0.125f, acc[i][1] * 0.125f,
                               acc[i][2] * 0.125f, acc[i][3] * 0.125f);
        *(float4*)&att[base] = v;
    }
}

// ---------------- row softmax over s; one block (128 thr) per row -----------
__global__ void softmax_rows(float* __restrict__ att) {
    float* row = att + (size_t)blockIdx.x * LSEQ;
    int tid = threadIdx.x;
    float v[8];
    #pragma unroll
    for (int i = 0; i < 8; i++) v[i] = row[tid + (i << 7)];
    float m = v[0];
    #pragma unroll
    for (int i = 1; i < 8; i++) m = fmaxf(m, v[i]);
    #pragma unroll
    for (int o = 16; o; o >>= 1) m = fmaxf(m, __shfl_xor_sync(0xffffffffu, m, o));
    __shared__ float sm[4], ssum[4];
    int wid = tid >> 5, lane = tid & 31;
    if (!lane) sm[wid] = m;
    __syncthreads();
    m = fmaxf(fmaxf(sm[0], sm[1]), fmaxf(sm[2], sm[3]));
    float s = 0.f;
    #pragma unroll
    for (int i = 0; i < 8; i++) { v[i] = __expf(v[i] - m); s += v[i]; }
    #pragma unroll
    for (int o = 16; o; o >>= 1) s += __shfl_xor_sync(0xffffffffu, s, o);
    if (!lane) ssum[wid] = s;
    __syncthreads();
    s = ssum[0] + ssum[1] + ssum[2] + ssum[3];
    float inv = 1.0f / s;
    #pragma unroll
    for (int i = 0; i < 8; i++) row[tid + (i << 7)] = v[i] * inv;
}

// ---------------- ao[b, h*64+c, t] = sum_s att[bh,t,s] v[c,s] ---------------
// block 256 (16x16), tile 64(c) x 64(t), BK=16; grid (LSEQ/64, BB*NH)
__global__ void attn_av(const float* __restrict__ qkv, const float* __restrict__ att,
                        float* __restrict__ ao) {
    __shared__ float Vs[16][64];
    __shared__ float Ps[16][64];
    int bh = blockIdx.y;
    int b = bh >> 4, hh = bh & 15;
    const float* V = qkv + ((size_t)b * 3 * CEMB + hh * 192 + 128) * LSEQ;
    int t0 = blockIdx.x << 6;
    int tid = threadIdx.x, tx = tid & 15, ty = tid >> 4;
    int r = tid >> 2;              // 0..63 : c for V, t for P
    int k4 = (tid & 3) << 2;       // 0,4,8,12

    float acc[4][4] = {};
    for (int s0 = 0; s0 < LSEQ; s0 += 16) {
        float4 v4 = *(const float4*)&V[(size_t)r * LSEQ + s0 + k4];
        float4 p4 = *(const float4*)&att[((size_t)bh * LSEQ + t0 + r) * LSEQ + s0 + k4];
        Vs[k4 + 0][r] = v4.x; Vs[k4 + 1][r] = v4.y; Vs[k4 + 2][r] = v4.z; Vs[k4 + 3][r] = v4.w;
        Ps[k4 + 0][r] = p4.x; Ps[k4 + 1][r] = p4.y; Ps[k4 + 2][r] = p4.z; Ps[k4 + 3][r] = p4.w;
        __syncthreads();
        #pragma unroll
        for (int k = 0; k < 16; k++) {
            float4 a  = *(const float4*)&Vs[k][ty << 2];
            float4 pv = *(const float4*)&Ps[k][tx << 2];
            fma44(acc, a, pv);
        }
        __syncthreads();
    }
    #pragma unroll
    for (int i = 0; i < 4; i++) {
        size_t base = ((size_t)b * CEMB + hh * 64 + (ty << 2) + i) * LSEQ + t0 + (tx << 2);
        *(float4*)&ao[base] = make_float4(acc[i][0], acc[i][1], acc[i][2], acc[i][3]);
    }
}

// ---------------- final: out[b,c] = x[b,c,0] --------------------------------
__global__ void take_col0(const float* __restrict__ x, float* __restrict__ out) {
    int i = blockIdx.x * 256 + threadIdx.x;  // 0..8191
    out[i] = x[(size_t)i * LSEQ];
}

extern "C" void kernel_launch(void* const* d_in, const int* in_sizes, int n_in,
                              void* d_out, int out_size) {
    const float* speech = (const float*)d_in[0];
    const float* init_w = (const float*)d_in[1];
    const float* init_b = (const float*)d_in[2];
    const float* gn_w   = (const float*)d_in[3];
    const float* gn_b   = (const float*)d_in[4];
    const float* qkv_w  = (const float*)d_in[5];
    const float* qkv_b  = (const float*)d_in[6];
    const float* proj_w = (const float*)d_in[7];
    const float* proj_b = (const float*)d_in[8];

    float *x, *h, *qkv, *att, *ao;
    cudaGetSymbolAddress((void**)&x,   g_x);
    cudaGetSymbolAddress((void**)&h,   g_h);
    cudaGetSymbolAddress((void**)&qkv, g_qkv);
    cudaGetSymbolAddress((void**)&att, g_att);
    cudaGetSymbolAddress((void**)&ao,  g_ao);

    init_gemm<<<dim3(LSEQ / 128, CEMB / 16, BB), 128>>>(speech, init_w, init_b, x);

    for (int i = 0; i < 6; i++) {
        group_norm_k<<<BB * NGRP, 256>>>(x, gn_w + (size_t)i * CEMB, gn_b + (size_t)i * CEMB, h);
        gemm_wx<false><<<dim3(LSEQ / 64, 3 * CEMB / 64, BB), 256>>>(
            qkv_w + (size_t)i * 3 * CEMB * CEMB, qkv_b + (size_t)i * 3 * CEMB,
            h, nullptr, qkv, 3 * CEMB, CEMB);
        attn_scores<<<dim3(LSEQ / 64, LSEQ / 64, BB * NH), 256>>>(qkv, att);
        softmax_rows<<<BB * NH * LSEQ, 128>>>(att);
        attn_av<<<dim3(LSEQ / 64, BB * NH), 256>>>(qkv, att, ao);
        gemm_wx<true><<<dim3(LSEQ / 64, CEMB / 64, BB), 256>>>(
            proj_w + (size_t)i * CEMB * CEMB, proj_b + (size_t)i * CEMB,
            ao, x, x, CEMB, CEMB);
    }

    take_col0<<<32, 256>>>(x, (float*)d_out);
}

// round 2
// speedup vs baseline: 2.9381x; 2.9381x over previous
#include <cuda_runtime.h>
#include <math.h>
#include <stdint.h>

#define LSEQ 1024
#define CEMB 1024
#define KD   1024
#define BB   8
#define NH   16
#define DH   64
#define NGRP 32

// ---------------- static scratch (device globals; no allocation) -------------
__device__ float g_x  [(size_t)BB * CEMB * LSEQ];        // 32 MB
__device__ float g_h  [(size_t)BB * CEMB * LSEQ];        // 32 MB
__device__ float g_qkv[(size_t)BB * 3 * CEMB * LSEQ];    // 96 MB
__device__ float g_att[(size_t)BB * NH * LSEQ * LSEQ];   // 512 MB
__device__ float g_ao [(size_t)BB * CEMB * LSEQ];        // 32 MB

// ---------------- tf32 helpers ----------------------------------------------
__device__ __forceinline__ uint32_t f2tf(float f) {
    uint32_t u;
    asm("cvt.rna.tf32.f32 %0, %1;" : "=r"(u) : "f"(f));
    return u;
}

__device__ __forceinline__ void mma_tf32(float (&c)[4],
                                         uint32_t a0, uint32_t a1, uint32_t a2, uint32_t a3,
                                         uint32_t b0, uint32_t b1) {
    asm volatile(
        "mma.sync.aligned.m16n8k8.row.col.f32.tf32.tf32.f32 "
        "{%0,%1,%2,%3},{%4,%5,%6,%7},{%8,%9},{%0,%1,%2,%3};"
        : "+f"(c[0]), "+f"(c[1]), "+f"(c[2]), "+f"(c[3])
        : "r"(a0), "r"(a1), "r"(a2), "r"(a3), "r"(b0), "r"(b1));
}

// ---------------- init projection: x[b,o,l] = sum_c W[o,c]*speech[b,c,l]+b[o]
__global__ void init_gemm(const float* __restrict__ speech, const float* __restrict__ W,
                          const float* __restrict__ bias, float* __restrict__ x) {
    __shared__ float Ws[16][80];
    __shared__ float Bs[16];
    int l  = blockIdx.x * 128 + threadIdx.x;
    int o0 = blockIdx.y * 16;
    int b  = blockIdx.z;
    for (int i = threadIdx.x; i < 16 * 80; i += 128)
        Ws[i / 80][i % 80] = W[(size_t)(o0 + i / 80) * 80 + (i % 80)];
    if (threadIdx.x < 16) Bs[threadIdx.x] = bias[o0 + threadIdx.x];
    __syncthreads();

    float acc[16];
    #pragma unroll
    for (int i = 0; i < 16; i++) acc[i] = Bs[i];
    const float* sp = speech + (size_t)b * 80 * LSEQ + l;
    for (int c = 0; c < 80; c++) {
        float sv = sp[(size_t)c * LSEQ];
        #pragma unroll
        for (int i = 0; i < 16; i++) acc[i] += Ws[i][c] * sv;
    }
    float* xp = x + ((size_t)b * CEMB + o0) * LSEQ + l;
    #pragma unroll
    for (int i = 0; i < 16; i++) xp[(size_t)i * LSEQ] = acc[i];
}

// ---------------- GroupNorm -------------------------------------------------
__global__ void group_norm_k(const float* __restrict__ x, const float* __restrict__ w,
                             const float* __restrict__ bb, float* __restrict__ h) {
    int bg = blockIdx.x;
    int b = bg >> 5, g = bg & 31;
    const float* xp = x + ((size_t)b * CEMB + g * 32) * LSEQ;
    float s = 0.f, ss = 0.f;
    for (int i = threadIdx.x; i < 32 * LSEQ; i += 256) {
        float v = xp[i];
        s += v; ss += v * v;
    }
    #pragma unroll
    for (int o = 16; o; o >>= 1) {
        s  += __shfl_down_sync(0xffffffffu, s,  o);
        ss += __shfl_down_sync(0xffffffffu, ss, o);
    }
    __shared__ float shs[8], shss[8];
    __shared__ float smean, srstd;
    int wid = threadIdx.x >> 5, lane = threadIdx.x & 31;
    if (!lane) { shs[wid] = s; shss[wid] = ss; }
    __syncthreads();
    if (threadIdx.x == 0) {
        float S = 0.f, SS = 0.f;
        #pragma unroll
        for (int i = 0; i < 8; i++) { S += shs[i]; SS += shss[i]; }
        float mean = S / 32768.f;
        float var  = SS / 32768.f - mean * mean;
        smean = mean;
        srstd = rsqrtf(var + 1e-5f);
    }
    __syncthreads();
    float mean = smean, rstd = srstd;
    float* hp = h + ((size_t)b * CEMB + g * 32) * LSEQ;
    for (int i = threadIdx.x; i < 32 * LSEQ; i += 256) {
        int c = g * 32 + (i >> 10);
        hp[i] = (xp[i] - mean) * rstd * w[c] + bb[c];
    }
}

// ---------------- tf32 MMA GEMM: Y[b,o,l] = sum_k W[o,k] X[b,k,l] + bias (+res)
// block 256 (8 warps, 2m x 4n), tile 128(o) x 128(l), BK=32
// A(W) smem [m][k] stride 36 ; B(X) smem [k][n] stride 136 — both conflict-free
template <bool RES>
__global__ __launch_bounds__(256, 2) void gemm_wx_mma(
    const float* __restrict__ W, const float* __restrict__ bias,
    const float* __restrict__ X, const float* __restrict__ res,
    float* __restrict__ Y, int O)
{
    __shared__ uint32_t As[128 * 36];
    __shared__ uint32_t Bs[32 * 136];
    int tid = threadIdx.x, lane = tid & 31, warp = tid >> 5;
    int g = lane >> 2, tg = lane & 3;
    int wm = warp >> 2, wn = warp & 3;
    int b = blockIdx.z, o0 = blockIdx.y << 7, l0 = blockIdx.x << 7;
    const float* Wp = W + (size_t)o0 * KD;
    const float* Xp = X + (size_t)b * KD * LSEQ + l0;

    float acc[4][4][4] = {};

    for (int k0 = 0; k0 < KD; k0 += 32) {
        float4 ra[4], rb[4];
        #pragma unroll
        for (int j = 0; j < 4; j++) {
            int idx = tid + (j << 8);
            int r  = idx >> 3, c  = (idx & 7)  << 2;
            int r2 = idx >> 5, c2 = (idx & 31) << 2;
            ra[j] = *(const float4*)(Wp + (size_t)r * KD + k0 + c);
            rb[j] = *(const float4*)(Xp + (size_t)(k0 + r2) * LSEQ + c2);
        }
        if (k0) __syncthreads();
        #pragma unroll
        for (int j = 0; j < 4; j++) {
            int idx = tid + (j << 8);
            int r  = idx >> 3, c  = (idx & 7)  << 2;
            int r2 = idx >> 5, c2 = (idx & 31) << 2;
            *(uint4*)&As[r * 36 + c]   = make_uint4(f2tf(ra[j].x), f2tf(ra[j].y), f2tf(ra[j].z), f2tf(ra[j].w));
            *(uint4*)&Bs[r2 * 136 + c2] = make_uint4(f2tf(rb[j].x), f2tf(rb[j].y), f2tf(rb[j].z), f2tf(rb[j].w));
        }
        __syncthreads();
        #pragma unroll
        for (int ks = 0; ks < 4; ks++) {
            int kk = ks << 3;
            uint32_t af[4][4], bf[4][2];
            #pragma unroll
            for (int mi = 0; mi < 4; mi++) {
                const uint32_t* p = &As[(wm * 64 + mi * 16 + g) * 36 + kk + tg];
                af[mi][0] = p[0]; af[mi][1] = p[8 * 36];
                af[mi][2] = p[4]; af[mi][3] = p[8 * 36 + 4];
            }
            #pragma unroll
            for (int ni = 0; ni < 4; ni++) {
                const uint32_t* p = &Bs[(kk + tg) * 136 + wn * 32 + ni * 8 + g];
                bf[ni][0] = p[0]; bf[ni][1] = p[4 * 136];
            }
            #pragma unroll
            for (int mi = 0; mi < 4; mi++)
                #pragma unroll
                for (int ni = 0; ni < 4; ni++)
                    mma_tf32(acc[mi][ni], af[mi][0], af[mi][1], af[mi][2], af[mi][3],
                             bf[ni][0], bf[ni][1]);
        }
    }

    #pragma unroll
    for (int mi = 0; mi < 4; mi++) {
        #pragma unroll
        for (int rr = 0; rr < 2; rr++) {
            int o = o0 + wm * 64 + mi * 16 + g + rr * 8;
            float bsv = bias[o];
            size_t rowoff = ((size_t)b * O + o) * LSEQ + l0;
            #pragma unroll
            for (int ni = 0; ni < 4; ni++) {
                int l = wn * 32 + ni * 8 + (tg << 1);
                float2 v = make_float2(acc[mi][ni][rr * 2] + bsv, acc[mi][ni][rr * 2 + 1] + bsv);
                if (RES) {
                    float2 rv = *(const float2*)(res + rowoff + l);
                    v.x += rv.x; v.y += rv.y;
                }
                *(float2*)(Y + rowoff + l) = v;
            }
        }
    }
}

// ---------------- att[bh,t,s] = 0.125 * sum_c q[c,t] k[c,s]  (tf32 mma) -----
// block 256, tile 128(t) x 128(s), k = 64 channels in 2 chunks of 32
// A(Q) smem [k][m] stride 136 (Q natural [c][t]); B(K) smem [k][n] stride 136
__global__ __launch_bounds__(256, 2) void attn_scores_mma(
    const float* __restrict__ qkv, float* __restrict__ att)
{
    __shared__ uint32_t Qs[32 * 136];
    __shared__ uint32_t Ks[32 * 136];
    int tid = threadIdx.x, lane = tid & 31, warp = tid >> 5;
    int g = lane >> 2, tg = lane & 3;
    int wm = warp >> 2, wn = warp & 3;
    int bh = blockIdx.z, b = bh >> 4, hh = bh & 15;
    int t0 = blockIdx.y << 7, s0 = blockIdx.x << 7;
    const float* Q  = qkv + ((size_t)b * 3 * CEMB + hh * 192) * LSEQ;
    const float* Kp = Q + (size_t)DH * LSEQ;

    float acc[4][4][4] = {};

    for (int c0 = 0; c0 < 64; c0 += 32) {
        float4 rq[4], rk[4];
        #pragma unroll
        for (int j = 0; j < 4; j++) {
            int idx = tid + (j << 8);
            int r = idx >> 5, cc = (idx & 31) << 2;
            rq[j] = *(const float4*)(Q  + (size_t)(c0 + r) * LSEQ + t0 + cc);
            rk[j] = *(const float4*)(Kp + (size_t)(c0 + r) * LSEQ + s0 + cc);
        }
        if (c0) __syncthreads();
        #pragma unroll
        for (int j = 0; j < 4; j++) {
            int idx = tid + (j << 8);
            int r = idx >> 5, cc = (idx & 31) << 2;
            *(uint4*)&Qs[r * 136 + cc] = make_uint4(f2tf(rq[j].x), f2tf(rq[j].y), f2tf(rq[j].z), f2tf(rq[j].w));
            *(uint4*)&Ks[r * 136 + cc] = make_uint4(f2tf(rk[j].x), f2tf(rk[j].y), f2tf(rk[j].z), f2tf(rk[j].w));
        }
        __syncthreads();
        #pragma unroll
        for (int ks = 0; ks < 4; ks++) {
            int kk = ks << 3;
            uint32_t af[4][4], bf[4][2];
            #pragma unroll
            for (int mi = 0; mi < 4; mi++) {
                const uint32_t* p = &Qs[(kk + tg) * 136 + wm * 64 + mi * 16 + g];
                af[mi][0] = p[0]; af[mi][1] = p[8];
                af[mi][2] = p[4 * 136]; af[mi][3] = p[4 * 136 + 8];
            }
            #pragma unroll
            for (int ni = 0; ni < 4; ni++) {
                const uint32_t* p = &Ks[(kk + tg) * 136 + wn * 32 + ni * 8 + g];
                bf[ni][0] = p[0]; bf[ni][1] = p[4 * 136];
            }
            #pragma unroll
            for (int mi = 0; mi < 4; mi++)
                #pragma unroll
                for (int ni = 0; ni < 4; ni++)
                    mma_tf32(acc[mi][ni], af[mi][0], af[mi][1], af[mi][2], af[mi][3],
                             bf[ni][0], bf[ni][1]);
        }
    }

    #pragma unroll
    for (int mi = 0; mi < 4; mi++) {
        #pragma unroll
        for (int rr = 0; rr < 2; rr++) {
            int t = t0 + wm * 64 + mi * 16 + g + rr * 8;
            size_t rowoff = ((size_t)bh * LSEQ + t) * LSEQ + s0;
            #pragma unroll
            for (int ni = 0; ni < 4; ni++) {
                int s = wn * 32 + ni * 8 + (tg << 1);
                *(float2*)(att + rowoff + s) =
                    make_float2(acc[mi][ni][rr * 2] * 0.125f, acc[mi][ni][rr * 2 + 1] * 0.125f);
            }
        }
    }
}

// ---------------- row softmax -----------------------------------------------
__global__ void softmax_rows(float* __restrict__ att) {
    float* row = att + (size_t)blockIdx.x * LSEQ;
    int tid = threadIdx.x;
    float v[8];
    #pragma unroll
    for (int i = 0; i < 8; i++) v[i] = row[tid + (i << 7)];
    float m = v[0];
    #pragma unroll
    for (int i = 1; i < 8; i++) m = fmaxf(m, v[i]);
    #pragma unroll
    for (int o = 16; o; o >>= 1) m = fmaxf(m, __shfl_xor_sync(0xffffffffu, m, o));
    __shared__ float sm[4], ssum[4];
    int wid = tid >> 5, lane = tid & 31;
    if (!lane) sm[wid] = m;
    __syncthreads();
    m = fmaxf(fmaxf(sm[0], sm[1]), fmaxf(sm[2], sm[3]));
    float s = 0.f;
    #pragma unroll
    for (int i = 0; i < 8; i++) { v[i] = __expf(v[i] - m); s += v[i]; }
    #pragma unroll
    for (int o = 16; o; o >>= 1) s += __shfl_xor_sync(0xffffffffu, s, o);
    if (!lane) ssum[wid] = s;
    __syncthreads();
    s = ssum[0] + ssum[1] + ssum[2] + ssum[3];
    float inv = 1.0f / s;
    #pragma unroll
    for (int i = 0; i < 8; i++) row[tid + (i << 7)] = v[i] * inv;
}

// ---------------- ao[b, h*64+c, t] = sum_s P[t,s] V[c,s]  (tf32 mma) --------
// block 256 (8 warps 2m x 4n), tile m=64(c) x n=128(t), BK=32 over s
// A(V) smem [m][k] stride 36 (V natural [c][s]); B(P) smem [n][k] stride 36
__global__ __launch_bounds__(256, 2) void attn_av_mma(
    const float* __restrict__ qkv, const float* __restrict__ att,
    float* __restrict__ ao)
{
    __shared__ uint32_t Vs[64 * 36];
    __shared__ uint32_t Ps[128 * 36];
    int tid = threadIdx.x, lane = tid & 31, warp = tid >> 5;
    int g = lane >> 2, tg = lane & 3;
    int wm = warp >> 2, wn = warp & 3;   // wm 0..1, wn 0..3
    int bh = blockIdx.y, b = bh >> 4, hh = bh & 15;
    int t0 = blockIdx.x << 7;
    const float* V = qkv + ((size_t)b * 3 * CEMB + hh * 192 + 128) * LSEQ;
    const float* P = att + ((size_t)bh * LSEQ + t0) * LSEQ;

    float acc[2][4][4] = {};

    for (int s0 = 0; s0 < LSEQ; s0 += 32) {
        float4 rv[2], rp[4];
        #pragma unroll
        for (int j = 0; j < 2; j++) {
            int idx = tid + (j << 8);
            int r = idx >> 3, c = (idx & 7) << 2;
            rv[j] = *(const float4*)(V + (size_t)r * LSEQ + s0 + c);
        }
        #pragma unroll
        for (int j = 0; j < 4; j++) {
            int idx = tid + (j << 8);
            int r = idx >> 3, c = (idx & 7) << 2;
            rp[j] = *(const float4*)(P + (size_t)r * LSEQ + s0 + c);
        }
        if (s0) __syncthreads();
        #pragma unroll
        for (int j = 0; j < 2; j++) {
            int idx = tid + (j << 8);
            int r = idx >> 3, c = (idx & 7) << 2;
            *(uint4*)&Vs[r * 36 + c] = make_uint4(f2tf(rv[j].x), f2tf(rv[j].y), f2tf(rv[j].z), f2tf(rv[j].w));
        }
        #pragma unroll
        for (int j = 0; j < 4; j++) {
            int idx = tid + (j << 8);
            int r = idx >> 3, c = (idx & 7) << 2;
            *(uint4*)&Ps[r * 36 + c] = make_uint4(f2tf(rp[j].x), f2tf(rp[j].y), f2tf(rp[j].z), f2tf(rp[j].w));
        }
        __syncthreads();
        #pragma unroll
        for (int ks = 0; ks < 4; ks++) {
            int kk = ks << 3;
            uint32_t af[2][4], bf[4][2];
            #pragma unroll
            for (int mi = 0; mi < 2; mi++) {
                const uint32_t* p = &Vs[(wm * 32 + mi * 16 + g) * 36 + kk + tg];
                af[mi][0] = p[0]; af[mi][1] = p[8 * 36];
                af[mi][2] = p[4]; af[mi][3] = p[8 * 36 + 4];
            }
            #pragma unroll
            for (int ni = 0; ni < 4; ni++) {
                const uint32_t* p = &Ps[(wn * 32 + ni * 8 + g) * 36 + kk + tg];
                bf[ni][0] = p[0]; bf[ni][1] = p[4];
            }
            #pragma unroll
            for (int mi = 0; mi < 2; mi++)
                #pragma unroll
                for (int ni = 0; ni < 4; ni++)
                    mma_tf32(acc[mi][ni], af[mi][0], af[mi][1], af[mi][2], af[mi][3],
                             bf[ni][0], bf[ni][1]);
        }
    }

    #pragma unroll
    for (int mi = 0; mi < 2; mi++) {
        #pragma unroll
        for (int rr = 0; rr < 2; rr++) {
            int c = hh * 64 + wm * 32 + mi * 16 + g + rr * 8;
            size_t rowoff = ((size_t)b * CEMB + c) * LSEQ + t0;
            #pragma unroll
            for (int ni = 0; ni < 4; ni++) {
                int t = wn * 32 + ni * 8 + (tg << 1);
                *(float2*)(ao + rowoff + t) =
                    make_float2(acc[mi][ni][rr * 2], acc[mi][ni][rr * 2 + 1]);
            }
        }
    }
}

// ---------------- final: out[b,c] = x[b,c,0] --------------------------------
__global__ void take_col0(const float* __restrict__ x, float* __restrict__ out) {
    int i = blockIdx.x * 256 + threadIdx.x;
    out[i] = x[(size_t)i * LSEQ];
}

extern "C" void kernel_launch(void* const* d_in, const int* in_sizes, int n_in,
                              void* d_out, int out_size) {
    const float* speech = (const float*)d_in[0];
    const float* init_w = (const float*)d_in[1];
    const float* init_b = (const float*)d_in[2];
    const float* gn_w   = (const float*)d_in[3];
    const float* gn_b   = (const float*)d_in[4];
    const float* qkv_w  = (const float*)d_in[5];
    const float* qkv_b  = (const float*)d_in[6];
    const float* proj_w = (const float*)d_in[7];
    const float* proj_b = (const float*)d_in[8];

    float *x, *h, *qkv, *att, *ao;
    cudaGetSymbolAddress((void**)&x,   g_x);
    cudaGetSymbolAddress((void**)&h,   g_h);
    cudaGetSymbolAddress((void**)&qkv, g_qkv);
    cudaGetSymbolAddress((void**)&att, g_att);
    cudaGetSymbolAddress((void**)&ao,  g_ao);

    init_gemm<<<dim3(LSEQ / 128, CEMB / 16, BB), 128>>>(speech, init_w, init_b, x);

    for (int i = 0; i < 6; i++) {
        group_norm_k<<<BB * NGRP, 256>>>(x, gn_w + (size_t)i * CEMB, gn_b + (size_t)i * CEMB, h);
        gemm_wx_mma<false><<<dim3(LSEQ / 128, 3 * CEMB / 128, BB), 256>>>(
            qkv_w + (size_t)i * 3 * CEMB * CEMB, qkv_b + (size_t)i * 3 * CEMB,
            h, nullptr, qkv, 3 * CEMB);
        attn_scores_mma<<<dim3(LSEQ / 128, LSEQ / 128, BB * NH), 256>>>(qkv, att);
        softmax_rows<<<BB * NH * LSEQ, 128>>>(att);
        attn_av_mma<<<dim3(LSEQ / 128, BB * NH), 256>>>(qkv, att, ao);
        gemm_wx_mma<true><<<dim3(LSEQ / 128, CEMB / 128, BB), 256>>>(
            proj_w + (size_t)i * CEMB * CEMB, proj_b + (size_t)i * CEMB,
            ao, x, x, CEMB);
    }

    take_col0<<<32, 256>>>(x, (float*)d_out);
}

// round 3
// speedup vs baseline: 3.7502x; 1.2764x over previous
#include <cuda_runtime.h>
#include <math.h>
#include <stdint.h>

#define LSEQ 1024
#define CEMB 1024
#define KD   1024
#define BB   8
#define NH   16
#define DH   64
#define NGRP 32

// ---------------- static scratch (device globals; no allocation) -------------
__device__ float g_x  [(size_t)BB * CEMB * LSEQ];        // 32 MB
__device__ float g_h  [(size_t)BB * CEMB * LSEQ];        // 32 MB
__device__ float g_qkv[(size_t)BB * 3 * CEMB * LSEQ];    // 96 MB
__device__ float g_ao [(size_t)BB * CEMB * LSEQ];        // 32 MB

// ---------------- tf32 helpers ----------------------------------------------
__device__ __forceinline__ uint32_t f2tf(float f) {
    uint32_t u;
    asm("cvt.rna.tf32.f32 %0, %1;" : "=r"(u) : "f"(f));
    return u;
}

__device__ __forceinline__ void mma_tf32(float (&c)[4],
                                         uint32_t a0, uint32_t a1, uint32_t a2, uint32_t a3,
                                         uint32_t b0, uint32_t b1) {
    asm volatile(
        "mma.sync.aligned.m16n8k8.row.col.f32.tf32.tf32.f32 "
        "{%0,%1,%2,%3},{%4,%5,%6,%7},{%8,%9},{%0,%1,%2,%3};"
        : "+f"(c[0]), "+f"(c[1]), "+f"(c[2]), "+f"(c[3])
        : "r"(a0), "r"(a1), "r"(a2), "r"(a3), "r"(b0), "r"(b1));
}

// ---------------- init projection -------------------------------------------
__global__ void init_gemm(const float* __restrict__ speech, const float* __restrict__ W,
                          const float* __restrict__ bias, float* __restrict__ x) {
    __shared__ float Ws[16][80];
    __shared__ float Bs[16];
    int l  = blockIdx.x * 128 + threadIdx.x;
    int o0 = blockIdx.y * 16;
    int b  = blockIdx.z;
    for (int i = threadIdx.x; i < 16 * 80; i += 128)
        Ws[i / 80][i % 80] = W[(size_t)(o0 + i / 80) * 80 + (i % 80)];
    if (threadIdx.x < 16) Bs[threadIdx.x] = bias[o0 + threadIdx.x];
    __syncthreads();

    float acc[16];
    #pragma unroll
    for (int i = 0; i < 16; i++) acc[i] = Bs[i];
    const float* sp = speech + (size_t)b * 80 * LSEQ + l;
    for (int c = 0; c < 80; c++) {
        float sv = sp[(size_t)c * LSEQ];
        #pragma unroll
        for (int i = 0; i < 16; i++) acc[i] += Ws[i][c] * sv;
    }
    float* xp = x + ((size_t)b * CEMB + o0) * LSEQ + l;
    #pragma unroll
    for (int i = 0; i < 16; i++) xp[(size_t)i * LSEQ] = acc[i];
}

// ---------------- GroupNorm -------------------------------------------------
__global__ void group_norm_k(const float* __restrict__ x, const float* __restrict__ w,
                             const float* __restrict__ bb, float* __restrict__ h) {
    int bg = blockIdx.x;
    int b = bg >> 5, g = bg & 31;
    const float* xp = x + ((size_t)b * CEMB + g * 32) * LSEQ;
    float s = 0.f, ss = 0.f;
    for (int i = threadIdx.x; i < 32 * LSEQ; i += 256) {
        float v = xp[i];
        s += v; ss += v * v;
    }
    #pragma unroll
    for (int o = 16; o; o >>= 1) {
        s  += __shfl_down_sync(0xffffffffu, s,  o);
        ss += __shfl_down_sync(0xffffffffu, ss, o);
    }
    __shared__ float shs[8], shss[8];
    __shared__ float smean, srstd;
    int wid = threadIdx.x >> 5, lane = threadIdx.x & 31;
    if (!lane) { shs[wid] = s; shss[wid] = ss; }
    __syncthreads();
    if (threadIdx.x == 0) {
        float S = 0.f, SS = 0.f;
        #pragma unroll
        for (int i = 0; i < 8; i++) { S += shs[i]; SS += shss[i]; }
        float mean = S / 32768.f;
        float var  = SS / 32768.f - mean * mean;
        smean = mean;
        srstd = rsqrtf(var + 1e-5f);
    }
    __syncthreads();
    float mean = smean, rstd = srstd;
    float* hp = h + ((size_t)b * CEMB + g * 32) * LSEQ;
    for (int i = threadIdx.x; i < 32 * LSEQ; i += 256) {
        int c = g * 32 + (i >> 10);
        hp[i] = (xp[i] - mean) * rstd * w[c] + bb[c];
    }
}

// ---------------- tf32 MMA GEMM (unchanged from R2) --------------------------
template <bool RES>
__global__ __launch_bounds__(256, 2) void gemm_wx_mma(
    const float* __restrict__ W, const float* __restrict__ bias,
    const float* __restrict__ X, const float* __restrict__ res,
    float* __restrict__ Y, int O)
{
    __shared__ uint32_t As[128 * 36];
    __shared__ uint32_t Bs[32 * 136];
    int tid = threadIdx.x, lane = tid & 31, warp = tid >> 5;
    int g = lane >> 2, tg = lane & 3;
    int wm = warp >> 2, wn = warp & 3;
    int b = blockIdx.z, o0 = blockIdx.y << 7, l0 = blockIdx.x << 7;
    const float* Wp = W + (size_t)o0 * KD;
    const float* Xp = X + (size_t)b * KD * LSEQ + l0;

    float acc[4][4][4] = {};

    for (int k0 = 0; k0 < KD; k0 += 32) {
        float4 ra[4], rb[4];
        #pragma unroll
        for (int j = 0; j < 4; j++) {
            int idx = tid + (j << 8);
            int r  = idx >> 3, c  = (idx & 7)  << 2;
            int r2 = idx >> 5, c2 = (idx & 31) << 2;
            ra[j] = *(const float4*)(Wp + (size_t)r * KD + k0 + c);
            rb[j] = *(const float4*)(Xp + (size_t)(k0 + r2) * LSEQ + c2);
        }
        if (k0) __syncthreads();
        #pragma unroll
        for (int j = 0; j < 4; j++) {
            int idx = tid + (j << 8);
            int r  = idx >> 3, c  = (idx & 7)  << 2;
            int r2 = idx >> 5, c2 = (idx & 31) << 2;
            *(uint4*)&As[r * 36 + c]   = make_uint4(f2tf(ra[j].x), f2tf(ra[j].y), f2tf(ra[j].z), f2tf(ra[j].w));
            *(uint4*)&Bs[r2 * 136 + c2] = make_uint4(f2tf(rb[j].x), f2tf(rb[j].y), f2tf(rb[j].z), f2tf(rb[j].w));
        }
        __syncthreads();
        #pragma unroll
        for (int ks = 0; ks < 4; ks++) {
            int kk = ks << 3;
            uint32_t af[4][4], bf[4][2];
            #pragma unroll
            for (int mi = 0; mi < 4; mi++) {
                const uint32_t* p = &As[(wm * 64 + mi * 16 + g) * 36 + kk + tg];
                af[mi][0] = p[0]; af[mi][1] = p[8 * 36];
                af[mi][2] = p[4]; af[mi][3] = p[8 * 36 + 4];
            }
            #pragma unroll
            for (int ni = 0; ni < 4; ni++) {
                const uint32_t* p = &Bs[(kk + tg) * 136 + wn * 32 + ni * 8 + g];
                bf[ni][0] = p[0]; bf[ni][1] = p[4 * 136];
            }
            #pragma unroll
            for (int mi = 0; mi < 4; mi++)
                #pragma unroll
                for (int ni = 0; ni < 4; ni++)
                    mma_tf32(acc[mi][ni], af[mi][0], af[mi][1], af[mi][2], af[mi][3],
                             bf[ni][0], bf[ni][1]);
        }
    }

    #pragma unroll
    for (int mi = 0; mi < 4; mi++) {
        #pragma unroll
        for (int rr = 0; rr < 2; rr++) {
            int o = o0 + wm * 64 + mi * 16 + g + rr * 8;
            float bsv = bias[o];
            size_t rowoff = ((size_t)b * O + o) * LSEQ + l0;
            #pragma unroll
            for (int ni = 0; ni < 4; ni++) {
                int l = wn * 32 + ni * 8 + (tg << 1);
                float2 v = make_float2(acc[mi][ni][rr * 2] + bsv, acc[mi][ni][rr * 2 + 1] + bsv);
                if (RES) {
                    float2 rv = *(const float2*)(res + rowoff + l);
                    v.x += rv.x; v.y += rv.y;
                }
                *(float2*)(Y + rowoff + l) = v;
            }
        }
    }
}

// ---------------- fused flash attention --------------------------------------
// One CTA per (bh, 128-query tile). 8 warps x 16 query rows; each warp spans
// the full 128-key width, so softmax reduces only within the 4-lane tg group.
// S = (Q^T K)/8 via tf32 mma; online softmax fp32; P->smem(tf32); O += P V^T.
// ao[b, h*64+c, t] output.
#define FA_QS 0                       // [64][136]  k=c, m=t   (A operand for S)
#define FA_KS 8704                    // [64][136]  k=c, n=s   (B operand for S)
#define FA_VS 17408                   // [64][132]  n=c, k=s   (B operand for PV)
#define FA_PS 25856                   // [128][132] m=t, k=s   (A operand for PV)
#define FA_SMEM ((25856 + 128 * 132) * 4)

__global__ __launch_bounds__(256, 1) void flash_attn(
    const float* __restrict__ qkv, float* __restrict__ ao)
{
    extern __shared__ uint32_t sm[];
    uint32_t* Qs = sm + FA_QS;
    uint32_t* Ks = sm + FA_KS;
    uint32_t* Vs = sm + FA_VS;
    uint32_t* Ps = sm + FA_PS;

    int tid = threadIdx.x, lane = tid & 31, warp = tid >> 5;
    int g = lane >> 2, tg = lane & 3;
    int tw = warp << 4;                      // warp's query-row offset (0..112)
    int bh = blockIdx.y, b = bh >> 4, hh = bh & 15;
    int t0 = blockIdx.x << 7;
    const float* Q  = qkv + ((size_t)b * 3 * CEMB + hh * 192) * LSEQ;
    const float* Kp = Q + (size_t)DH * LSEQ;
    const float* Vp = Q + (size_t)(2 * DH) * LSEQ;

    // load Q tile [64c x 128t]
    #pragma unroll
    for (int j = 0; j < 8; j++) {
        int idx = tid + (j << 8);
        int r = idx >> 5, c4 = (idx & 31) << 2;
        float4 q4 = *(const float4*)(Q + (size_t)r * LSEQ + t0 + c4);
        *(uint4*)&Qs[r * 136 + c4] = make_uint4(f2tf(q4.x), f2tf(q4.y), f2tf(q4.z), f2tf(q4.w));
    }
    __syncthreads();

    float accO[8][4] = {};
    float m0 = -1e30f, m1 = -1e30f, l0 = 0.f, l1 = 0.f;

    for (int s0 = 0; s0 < LSEQ; s0 += 128) {
        // load K, V tiles [64c x 128s]
        #pragma unroll
        for (int j = 0; j < 8; j++) {
            int idx = tid + (j << 8);
            int r = idx >> 5, c4 = (idx & 31) << 2;
            float4 k4 = *(const float4*)(Kp + (size_t)r * LSEQ + s0 + c4);
            float4 v4 = *(const float4*)(Vp + (size_t)r * LSEQ + s0 + c4);
            *(uint4*)&Ks[r * 136 + c4] = make_uint4(f2tf(k4.x), f2tf(k4.y), f2tf(k4.z), f2tf(k4.w));
            *(uint4*)&Vs[r * 132 + c4] = make_uint4(f2tf(v4.x), f2tf(v4.y), f2tf(v4.z), f2tf(v4.w));
        }
        __syncthreads();

        // S[16t x 128s] per warp
        float accS[16][4] = {};
        #pragma unroll
        for (int kk = 0; kk < 8; kk++) {
            const uint32_t* p = &Qs[(kk * 8 + tg) * 136 + tw + g];
            uint32_t a0 = p[0], a1 = p[8], a2 = p[4 * 136], a3 = p[4 * 136 + 8];
            #pragma unroll
            for (int ni = 0; ni < 16; ni++) {
                const uint32_t* q = &Ks[(kk * 8 + tg) * 136 + ni * 8 + g];
                mma_tf32(accS[ni], a0, a1, a2, a3, q[0], q[4 * 136]);
            }
        }

        // scale + online softmax (rows t = tw+g, tw+g+8)
        float tm0 = -1e30f, tm1 = -1e30f;
        #pragma unroll
        for (int ni = 0; ni < 16; ni++) {
            #pragma unroll
            for (int v = 0; v < 4; v++) accS[ni][v] *= 0.125f;
            tm0 = fmaxf(tm0, fmaxf(accS[ni][0], accS[ni][1]));
            tm1 = fmaxf(tm1, fmaxf(accS[ni][2], accS[ni][3]));
        }
        tm0 = fmaxf(tm0, __shfl_xor_sync(0xffffffffu, tm0, 1));
        tm0 = fmaxf(tm0, __shfl_xor_sync(0xffffffffu, tm0, 2));
        tm1 = fmaxf(tm1, __shfl_xor_sync(0xffffffffu, tm1, 1));
        tm1 = fmaxf(tm1, __shfl_xor_sync(0xffffffffu, tm1, 2));
        float nm0 = fmaxf(m0, tm0), nm1 = fmaxf(m1, tm1);
        float f0 = __expf(m0 - nm0), f1 = __expf(m1 - nm1);
        float ts0 = 0.f, ts1 = 0.f;
        #pragma unroll
        for (int ni = 0; ni < 16; ni++) {
            float p0 = __expf(accS[ni][0] - nm0);
            float p1 = __expf(accS[ni][1] - nm0);
            float p2 = __expf(accS[ni][2] - nm1);
            float p3 = __expf(accS[ni][3] - nm1);
            ts0 += p0 + p1; ts1 += p2 + p3;
            *(uint2*)&Ps[(tw + g) * 132 + ni * 8 + tg * 2]     = make_uint2(f2tf(p0), f2tf(p1));
            *(uint2*)&Ps[(tw + g + 8) * 132 + ni * 8 + tg * 2] = make_uint2(f2tf(p2), f2tf(p3));
        }
        ts0 += __shfl_xor_sync(0xffffffffu, ts0, 1);
        ts0 += __shfl_xor_sync(0xffffffffu, ts0, 2);
        ts1 += __shfl_xor_sync(0xffffffffu, ts1, 1);
        ts1 += __shfl_xor_sync(0xffffffffu, ts1, 2);
        l0 = l0 * f0 + ts0;
        l1 = l1 * f1 + ts1;
        m0 = nm0; m1 = nm1;
        #pragma unroll
        for (int ni = 0; ni < 8; ni++) {
            accO[ni][0] *= f0; accO[ni][1] *= f0;
            accO[ni][2] *= f1; accO[ni][3] *= f1;
        }
        __syncwarp();

        // O[16t x 64c] += P V^T  (k = s, 16 k-steps)
        #pragma unroll
        for (int kk = 0; kk < 16; kk++) {
            const uint32_t* p = &Ps[(tw + g) * 132 + kk * 8 + tg];
            uint32_t a0 = p[0], a1 = p[8 * 132], a2 = p[4], a3 = p[8 * 132 + 4];
            #pragma unroll
            for (int ni = 0; ni < 8; ni++) {
                const uint32_t* q = &Vs[(ni * 8 + g) * 132 + kk * 8 + tg];
                mma_tf32(accO[ni], a0, a1, a2, a3, q[0], q[4]);
            }
        }
        __syncthreads();
    }

    // epilogue: normalize and write ao[b, hh*64+c, t]
    float inv0 = 1.0f / l0, inv1 = 1.0f / l1;
    size_t base = ((size_t)b * CEMB + hh * 64) * LSEQ + t0 + tw + g;
    #pragma unroll
    for (int ni = 0; ni < 8; ni++) {
        int c = ni * 8 + tg * 2;
        ao[base + (size_t)c * LSEQ]           = accO[ni][0] * inv0;
        ao[base + (size_t)(c + 1) * LSEQ]     = accO[ni][1] * inv0;
        ao[base + (size_t)c * LSEQ + 8]       = accO[ni][2] * inv1;
        ao[base + (size_t)(c + 1) * LSEQ + 8] = accO[ni][3] * inv1;
    }
}

// ---------------- final: out[b,c] = x[b,c,0] --------------------------------
__global__ void take_col0(const float* __restrict__ x, float* __restrict__ out) {
    int i = blockIdx.x * 256 + threadIdx.x;
    out[i] = x[(size_t)i * LSEQ];
}

extern "C" void kernel_launch(void* const* d_in, const int* in_sizes, int n_in,
                              void* d_out, int out_size) {
    const float* speech = (const float*)d_in[0];
    const float* init_w = (const float*)d_in[1];
    const float* init_b = (const float*)d_in[2];
    const float* gn_w   = (const float*)d_in[3];
    const float* gn_b   = (const float*)d_in[4];
    const float* qkv_w  = (const float*)d_in[5];
    const float* qkv_b  = (const float*)d_in[6];
    const float* proj_w = (const float*)d_in[7];
    const float* proj_b = (const float*)d_in[8];

    float *x, *h, *qkv, *ao;
    cudaGetSymbolAddress((void**)&x,   g_x);
    cudaGetSymbolAddress((void**)&h,   g_h);
    cudaGetSymbolAddress((void**)&qkv, g_qkv);
    cudaGetSymbolAddress((void**)&ao,  g_ao);

    cudaFuncSetAttribute(flash_attn, cudaFuncAttributeMaxDynamicSharedMemorySize, FA_SMEM);

    init_gemm<<<dim3(LSEQ / 128, CEMB / 16, BB), 128>>>(speech, init_w, init_b, x);

    for (int i = 0; i < 6; i++) {
        group_norm_k<<<BB * NGRP, 256>>>(x, gn_w + (size_t)i * CEMB, gn_b + (size_t)i * CEMB, h);
        gemm_wx_mma<false><<<dim3(LSEQ / 128, 3 * CEMB / 128, BB), 256>>>(
            qkv_w + (size_t)i * 3 * CEMB * CEMB, qkv_b + (size_t)i * 3 * CEMB,
            h, nullptr, qkv, 3 * CEMB);
        flash_attn<<<dim3(LSEQ / 128, BB * NH), 256, FA_SMEM>>>(qkv, ao);
        gemm_wx_mma<true><<<dim3(LSEQ / 128, CEMB / 128, BB), 256>>>(
            proj_w + (size_t)i * CEMB * CEMB, proj_b + (size_t)i * CEMB,
            ao, x, x, CEMB);
    }

    take_col0<<<32, 256>>>(x, (float*)d_out);
}

// round 4
// speedup vs baseline: 3.8093x; 1.0158x over previous
#include <cuda_runtime.h>
#include <math.h>
#include <stdint.h>

#define LSEQ 1024
#define CEMB 1024
#define KD   1024
#define BB   8
#define NH   16
#define DH   64
#define NGRP 32

// ---------------- static scratch (device globals; no allocation) -------------
__device__ float    g_x  [(size_t)BB * CEMB * LSEQ];          // 32 MB
__device__ float    g_h  [(size_t)BB * CEMB * LSEQ];          // 32 MB (tf32-rounded)
__device__ float    g_qkv[(size_t)BB * 3 * CEMB * LSEQ];      // 96 MB (tf32-rounded)
__device__ float    g_ao [(size_t)BB * CEMB * LSEQ];          // 32 MB (tf32-rounded)
__device__ uint32_t g_wq [(size_t)6 * 3 * CEMB * CEMB];       // 75.5 MB tf32 bits
__device__ uint32_t g_wp [(size_t)6 * CEMB * CEMB];           // 25.2 MB tf32 bits

// ---------------- helpers ----------------------------------------------------
__device__ __forceinline__ uint32_t f2tf(float f) {
    uint32_t u;
    asm("cvt.rna.tf32.f32 %0, %1;" : "=r"(u) : "f"(f));
    return u;
}

__device__ __forceinline__ void mma_tf32(float (&c)[4],
                                         uint32_t a0, uint32_t a1, uint32_t a2, uint32_t a3,
                                         uint32_t b0, uint32_t b1) {
    asm volatile(
        "mma.sync.aligned.m16n8k8.row.col.f32.tf32.tf32.f32 "
        "{%0,%1,%2,%3},{%4,%5,%6,%7},{%8,%9},{%0,%1,%2,%3};"
        : "+f"(c[0]), "+f"(c[1]), "+f"(c[2]), "+f"(c[3])
        : "r"(a0), "r"(a1), "r"(a2), "r"(a3), "r"(b0), "r"(b1));
}

__device__ __forceinline__ void cpa16(uint32_t dst, const void* src) {
    asm volatile("cp.async.cg.shared.global [%0], [%1], 16;" :: "r"(dst), "l"(src));
}
__device__ __forceinline__ void cpa_commit() {
    asm volatile("cp.async.commit_group;" ::);
}
template <int N>
__device__ __forceinline__ void cpa_wait() {
    asm volatile("cp.async.wait_group %0;" :: "n"(N));
}

// ---------------- weight pre-round (runs every launch; deterministic) --------
__global__ void round_tf32(const float* __restrict__ in, uint32_t* __restrict__ out, int n) {
    for (int i = blockIdx.x * 256 + threadIdx.x; i < n; i += gridDim.x * 256)
        out[i] = f2tf(in[i]);
}

// ---------------- init projection -------------------------------------------
__global__ void init_gemm(const float* __restrict__ speech, const float* __restrict__ W,
                          const float* __restrict__ bias, float* __restrict__ x) {
    __shared__ float Ws[16][80];
    __shared__ float Bs[16];
    int l  = blockIdx.x * 128 + threadIdx.x;
    int o0 = blockIdx.y * 16;
    int b  = blockIdx.z;
    for (int i = threadIdx.x; i < 16 * 80; i += 128)
        Ws[i / 80][i % 80] = W[(size_t)(o0 + i / 80) * 80 + (i % 80)];
    if (threadIdx.x < 16) Bs[threadIdx.x] = bias[o0 + threadIdx.x];
    __syncthreads();

    float acc[16];
    #pragma unroll
    for (int i = 0; i < 16; i++) acc[i] = Bs[i];
    const float* sp = speech + (size_t)b * 80 * LSEQ + l;
    for (int c = 0; c < 80; c++) {
        float sv = sp[(size_t)c * LSEQ];
        #pragma unroll
        for (int i = 0; i < 16; i++) acc[i] += Ws[i][c] * sv;
    }
    float* xp = x + ((size_t)b * CEMB + o0) * LSEQ + l;
    #pragma unroll
    for (int i = 0; i < 16; i++) xp[(size_t)i * LSEQ] = acc[i];
}

// ---------------- GroupNorm (writes tf32-rounded h) --------------------------
__global__ void group_norm_k(const float* __restrict__ x, const float* __restrict__ w,
                             const float* __restrict__ bb, float* __restrict__ h) {
    int bg = blockIdx.x;
    int b = bg >> 5, g = bg & 31;
    const float* xp = x + ((size_t)b * CEMB + g * 32) * LSEQ;
    float s = 0.f, ss = 0.f;
    for (int i = threadIdx.x; i < 32 * LSEQ; i += 256) {
        float v = xp[i];
        s += v; ss += v * v;
    }
    #pragma unroll
    for (int o = 16; o; o >>= 1) {
        s  += __shfl_down_sync(0xffffffffu, s,  o);
        ss += __shfl_down_sync(0xffffffffu, ss, o);
    }
    __shared__ float shs[8], shss[8];
    __shared__ float smean, srstd;
    int wid = threadIdx.x >> 5, lane = threadIdx.x & 31;
    if (!lane) { shs[wid] = s; shss[wid] = ss; }
    __syncthreads();
    if (threadIdx.x == 0) {
        float S = 0.f, SS = 0.f;
        #pragma unroll
        for (int i = 0; i < 8; i++) { S += shs[i]; SS += shss[i]; }
        float mean = S / 32768.f;
        float var  = SS / 32768.f - mean * mean;
        smean = mean;
        srstd = rsqrtf(var + 1e-5f);
    }
    __syncthreads();
    float mean = smean, rstd = srstd;
    float* hp = h + ((size_t)b * CEMB + g * 32) * LSEQ;
    for (int i = threadIdx.x; i < 32 * LSEQ; i += 256) {
        int c = g * 32 + (i >> 10);
        hp[i] = __uint_as_float(f2tf((xp[i] - mean) * rstd * w[c] + bb[c]));
    }
}

// ---------------- tf32 MMA GEMM with 3-stage cp.async pipeline ---------------
// Y[b,o,l] = sum_k W[o,k] X[b,k,l] + bias (+res). W pre-rounded tf32 bits,
// X tf32-rounded floats. Tile 128x128, BK=32, 8 warps (2m x 4n).
// Buffer: As[128][36] + Bs[32][136] = 8960 words; 3 stages = 105 KB dyn smem.
#define GEMM_BUF_W 8960
#define GEMM_SMEM  (GEMM_BUF_W * 3 * 4)

template <bool RES, bool ROUND>
__global__ __launch_bounds__(256, 2) void gemm_wx_mma(
    const uint32_t* __restrict__ W, const float* __restrict__ bias,
    const float* __restrict__ X, const float* __restrict__ res,
    float* __restrict__ Y, int O)
{
    extern __shared__ uint32_t smbuf[];
    int tid = threadIdx.x, lane = tid & 31, warp = tid >> 5;
    int g = lane >> 2, tg = lane & 3;
    int wm = warp >> 2, wn = warp & 3;
    int b = blockIdx.z, o0 = blockIdx.y << 7, l0 = blockIdx.x << 7;
    const uint32_t* Wp = W + (size_t)o0 * KD;
    const float* Xp = X + (size_t)b * KD * LSEQ + l0;
    uint32_t sb = (uint32_t)__cvta_generic_to_shared(smbuf);

    auto prefetch = [&](int kc, int bufi) {
        uint32_t base = sb + (uint32_t)bufi * (GEMM_BUF_W * 4u);
        int k0 = kc << 5;
        #pragma unroll
        for (int j = 0; j < 4; j++) {
            int idx = tid + (j << 8);
            int r = idx >> 3, c = (idx & 7) << 2;
            cpa16(base + (uint32_t)(r * 36 + c) * 4u, Wp + (size_t)r * KD + k0 + c);
        }
        #pragma unroll
        for (int j = 0; j < 4; j++) {
            int idx = tid + (j << 8);
            int r2 = idx >> 5, c2 = (idx & 31) << 2;
            cpa16(base + (uint32_t)(4608 + r2 * 136 + c2) * 4u,
                  Xp + (size_t)(k0 + r2) * LSEQ + c2);
        }
        cpa_commit();
    };

    float acc[4][4][4] = {};
    prefetch(0, 0);
    prefetch(1, 1);
    int use = 0, pre = 2;

    for (int kc = 0; kc < 32; kc++) {
        if (kc < 30) cpa_wait<1>(); else cpa_wait<0>();
        __syncthreads();
        if (kc < 30) prefetch(kc + 2, pre);

        const uint32_t* As = smbuf + use * GEMM_BUF_W;
        const uint32_t* Bs = As + 4608;
        #pragma unroll
        for (int ks = 0; ks < 4; ks++) {
            int kk = ks << 3;
            uint32_t af[4][4], bf[4][2];
            #pragma unroll
            for (int mi = 0; mi < 4; mi++) {
                const uint32_t* p = &As[(wm * 64 + mi * 16 + g) * 36 + kk + tg];
                af[mi][0] = p[0]; af[mi][1] = p[8 * 36];
                af[mi][2] = p[4]; af[mi][3] = p[8 * 36 + 4];
            }
            #pragma unroll
            for (int ni = 0; ni < 4; ni++) {
                const uint32_t* p = &Bs[(kk + tg) * 136 + wn * 32 + ni * 8 + g];
                bf[ni][0] = p[0]; bf[ni][1] = p[4 * 136];
            }
            #pragma unroll
            for (int mi = 0; mi < 4; mi++)
                #pragma unroll
                for (int ni = 0; ni < 4; ni++)
                    mma_tf32(acc[mi][ni], af[mi][0], af[mi][1], af[mi][2], af[mi][3],
                             bf[ni][0], bf[ni][1]);
        }
        use = (use == 2) ? 0 : use + 1;
        pre = (pre == 2) ? 0 : pre + 1;
    }

    #pragma unroll
    for (int mi = 0; mi < 4; mi++) {
        #pragma unroll
        for (int rr = 0; rr < 2; rr++) {
            int o = o0 + wm * 64 + mi * 16 + g + rr * 8;
            float bsv = bias[o];
            size_t rowoff = ((size_t)b * O + o) * LSEQ + l0;
            #pragma unroll
            for (int ni = 0; ni < 4; ni++) {
                int l = wn * 32 + ni * 8 + (tg << 1);
                float2 v = make_float2(acc[mi][ni][rr * 2] + bsv, acc[mi][ni][rr * 2 + 1] + bsv);
                if (RES) {
                    float2 rv = *(const float2*)(res + rowoff + l);
                    v.x += rv.x; v.y += rv.y;
                }
                if (ROUND) {
                    v.x = __uint_as_float(f2tf(v.x));
                    v.y = __uint_as_float(f2tf(v.y));
                }
                *(float2*)(Y + rowoff + l) = v;
            }
        }
    }
}

// ---------------- fused flash attention (cp.async loads) ---------------------
#define FA_QS 0                       // [64][136]  k=c, m=t
#define FA_KS 8704                    // [64][136]  k=c, n=s
#define FA_VS 17408                   // [64][132]  n=c, k=s
#define FA_PS 25856                   // [128][132] m=t, k=s
#define FA_SMEM ((25856 + 128 * 132) * 4)

__global__ __launch_bounds__(256, 1) void flash_attn(
    const float* __restrict__ qkv, float* __restrict__ ao)
{
    extern __shared__ uint32_t sm[];
    uint32_t* Qs = sm + FA_QS;
    uint32_t* Ks = sm + FA_KS;
    uint32_t* Vs = sm + FA_VS;
    uint32_t* Ps = sm + FA_PS;
    uint32_t fb = (uint32_t)__cvta_generic_to_shared(sm);

    int tid = threadIdx.x, lane = tid & 31, warp = tid >> 5;
    int g = lane >> 2, tg = lane & 3;
    int tw = warp << 4;
    int bh = blockIdx.y, b = bh >> 4, hh = bh & 15;
    int t0 = blockIdx.x << 7;
    const float* Q  = qkv + ((size_t)b * 3 * CEMB + hh * 192) * LSEQ;
    const float* Kp = Q + (size_t)DH * LSEQ;
    const float* Vp = Q + (size_t)(2 * DH) * LSEQ;

    // prologue: Q tile + first K/V tile in one group
    #pragma unroll
    for (int j = 0; j < 8; j++) {
        int idx = tid + (j << 8);
        int r = idx >> 5, c4 = (idx & 31) << 2;
        cpa16(fb + (uint32_t)(FA_QS + r * 136 + c4) * 4u, Q  + (size_t)r * LSEQ + t0 + c4);
        cpa16(fb + (uint32_t)(FA_KS + r * 136 + c4) * 4u, Kp + (size_t)r * LSEQ + c4);
        cpa16(fb + (uint32_t)(FA_VS + r * 132 + c4) * 4u, Vp + (size_t)r * LSEQ + c4);
    }
    cpa_commit();

    float accO[8][4] = {};
    float m0 = -1e30f, m1 = -1e30f, l0 = 0.f, l1 = 0.f;

    for (int s0 = 0; s0 < LSEQ; s0 += 128) {
        cpa_wait<0>();
        __syncthreads();

        // S[16t x 128s] per warp
        float accS[16][4] = {};
        #pragma unroll
        for (int kk = 0; kk < 8; kk++) {
            const uint32_t* p = &Qs[(kk * 8 + tg) * 136 + tw + g];
            uint32_t a0 = p[0], a1 = p[8], a2 = p[4 * 136], a3 = p[4 * 136 + 8];
            #pragma unroll
            for (int ni = 0; ni < 16; ni++) {
                const uint32_t* q = &Ks[(kk * 8 + tg) * 136 + ni * 8 + g];
                mma_tf32(accS[ni], a0, a1, a2, a3, q[0], q[4 * 136]);
            }
        }

        // online softmax (rows t = tw+g, tw+g+8)
        float tm0 = -1e30f, tm1 = -1e30f;
        #pragma unroll
        for (int ni = 0; ni < 16; ni++) {
            #pragma unroll
            for (int v = 0; v < 4; v++) accS[ni][v] *= 0.125f;
            tm0 = fmaxf(tm0, fmaxf(accS[ni][0], accS[ni][1]));
            tm1 = fmaxf(tm1, fmaxf(accS[ni][2], accS[ni][3]));
        }
        tm0 = fmaxf(tm0, __shfl_xor_sync(0xffffffffu, tm0, 1));
        tm0 = fmaxf(tm0, __shfl_xor_sync(0xffffffffu, tm0, 2));
        tm1 = fmaxf(tm1, __shfl_xor_sync(0xffffffffu, tm1, 1));
        tm1 = fmaxf(tm1, __shfl_xor_sync(0xffffffffu, tm1, 2));
        float nm0 = fmaxf(m0, tm0), nm1 = fmaxf(m1, tm1);
        float f0 = __expf(m0 - nm0), f1 = __expf(m1 - nm1);
        float ts0 = 0.f, ts1 = 0.f;
        #pragma unroll
        for (int ni = 0; ni < 16; ni++) {
            float p0 = __expf(accS[ni][0] - nm0);
            float p1 = __expf(accS[ni][1] - nm0);
            float p2 = __expf(accS[ni][2] - nm1);
            float p3 = __expf(accS[ni][3] - nm1);
            ts0 += p0 + p1; ts1 += p2 + p3;
            *(uint2*)&Ps[(tw + g) * 132 + ni * 8 + tg * 2]     = make_uint2(f2tf(p0), f2tf(p1));
            *(uint2*)&Ps[(tw + g + 8) * 132 + ni * 8 + tg * 2] = make_uint2(f2tf(p2), f2tf(p3));
        }
        ts0 += __shfl_xor_sync(0xffffffffu, ts0, 1);
        ts0 += __shfl_xor_sync(0xffffffffu, ts0, 2);
        ts1 += __shfl_xor_sync(0xffffffffu, ts1, 1);
        ts1 += __shfl_xor_sync(0xffffffffu, ts1, 2);
        l0 = l0 * f0 + ts0;
        l1 = l1 * f1 + ts1;
        m0 = nm0; m1 = nm1;
        #pragma unroll
        for (int ni = 0; ni < 8; ni++) {
            accO[ni][0] *= f0; accO[ni][1] *= f0;
            accO[ni][2] *= f1; accO[ni][3] *= f1;
        }
        __syncwarp();

        // O[16t x 64c] += P V^T
        #pragma unroll
        for (int kk = 0; kk < 16; kk++) {
            const uint32_t* p = &Ps[(tw + g) * 132 + kk * 8 + tg];
            uint32_t a0 = p[0], a1 = p[8 * 132], a2 = p[4], a3 = p[8 * 132 + 4];
            #pragma unroll
            for (int ni = 0; ni < 8; ni++) {
                const uint32_t* q = &Vs[(ni * 8 + g) * 132 + kk * 8 + tg];
                mma_tf32(accO[ni], a0, a1, a2, a3, q[0], q[4]);
            }
        }
        __syncthreads();

        if (s0 + 128 < LSEQ) {
            int sn = s0 + 128;
            #pragma unroll
            for (int j = 0; j < 8; j++) {
                int idx = tid + (j << 8);
                int r = idx >> 5, c4 = (idx & 31) << 2;
                cpa16(fb + (uint32_t)(FA_KS + r * 136 + c4) * 4u, Kp + (size_t)r * LSEQ + sn + c4);
                cpa16(fb + (uint32_t)(FA_VS + r * 132 + c4) * 4u, Vp + (size_t)r * LSEQ + sn + c4);
            }
            cpa_commit();
        }
    }

    // epilogue: normalize, round to tf32, write ao[b, hh*64+c, t]
    float inv0 = 1.0f / l0, inv1 = 1.0f / l1;
    size_t base = ((size_t)b * CEMB + hh * 64) * LSEQ + t0 + tw + g;
    #pragma unroll
    for (int ni = 0; ni < 8; ni++) {
        int c = ni * 8 + tg * 2;
        ao[base + (size_t)c * LSEQ]           = __uint_as_float(f2tf(accO[ni][0] * inv0));
        ao[base + (size_t)(c + 1) * LSEQ]     = __uint_as_float(f2tf(accO[ni][1] * inv0));
        ao[base + (size_t)c * LSEQ + 8]       = __uint_as_float(f2tf(accO[ni][2] * inv1));
        ao[base + (size_t)(c + 1) * LSEQ + 8] = __uint_as_float(f2tf(accO[ni][3] * inv1));
    }
}

// ---------------- final: out[b,c] = x[b,c,0] --------------------------------
__global__ void take_col0(const float* __restrict__ x, float* __restrict__ out) {
    int i = blockIdx.x * 256 + threadIdx.x;
    out[i] = x[(size_t)i * LSEQ];
}

extern "C" void kernel_launch(void* const* d_in, const int* in_sizes, int n_in,
                              void* d_out, int out_size) {
    const float* speech = (const float*)d_in[0];
    const float* init_w = (const float*)d_in[1];
    const float* init_b = (const float*)d_in[2];
    const float* gn_w   = (const float*)d_in[3];
    const float* gn_b   = (const float*)d_in[4];
    const float* qkv_w  = (const float*)d_in[5];
    const float* qkv_b  = (const float*)d_in[6];
    const float* proj_w = (const float*)d_in[7];
    const float* proj_b = (const float*)d_in[8];

    float *x, *h, *qkv, *ao;
    uint32_t *wq, *wp;
    cudaGetSymbolAddress((void**)&x,   g_x);
    cudaGetSymbolAddress((void**)&h,   g_h);
    cudaGetSymbolAddress((void**)&qkv, g_qkv);
    cudaGetSymbolAddress((void**)&ao,  g_ao);
    cudaGetSymbolAddress((void**)&wq,  g_wq);
    cudaGetSymbolAddress((void**)&wp,  g_wp);

    cudaFuncSetAttribute(flash_attn, cudaFuncAttributeMaxDynamicSharedMemorySize, FA_SMEM);
    cudaFuncSetAttribute(gemm_wx_mma<false, true>, cudaFuncAttributeMaxDynamicSharedMemorySize, GEMM_SMEM);
    cudaFuncSetAttribute(gemm_wx_mma<true, false>, cudaFuncAttributeMaxDynamicSharedMemorySize, GEMM_SMEM);

    round_tf32<<<2048, 256>>>(qkv_w,  wq, 6 * 3 * CEMB * CEMB);
    round_tf32<<<1024, 256>>>(proj_w, wp, 6 * CEMB * CEMB);

    init_gemm<<<dim3(LSEQ / 128, CEMB / 16, BB), 128>>>(speech, init_w, init_b, x);

    for (int i = 0; i < 6; i++) {
        group_norm_k<<<BB * NGRP, 256>>>(x, gn_w + (size_t)i * CEMB, gn_b + (size_t)i * CEMB, h);
        gemm_wx_mma<false, true><<<dim3(LSEQ / 128, 3 * CEMB / 128, BB), 256, GEMM_SMEM>>>(
            wq + (size_t)i * 3 * CEMB * CEMB, qkv_b + (size_t)i * 3 * CEMB,
            h, nullptr, qkv, 3 * CEMB);
        flash_attn<<<dim3(LSEQ / 128, BB * NH), 256, FA_SMEM>>>(qkv, ao);
        gemm_wx_mma<true, false><<<dim3(LSEQ / 128, CEMB / 128, BB), 256, GEMM_SMEM>>>(
            wp + (size_t)i * CEMB * CEMB, proj_b + (size_t)i * CEMB,
            ao, x, x, CEMB);
    }

    take_col0<<<32, 256>>>(x, (float*)d_out);
}